// round 2
// baseline (speedup 1.0000x reference)
#include <cuda_runtime.h>
#include <cstdint>
#include <cmath>

#define T_STEPS 4096
#define HH      1024
#define G4      4096          // 4*H gate rows
#define NCTA    128
#define UPC     8             // hidden units per CTA (1024/128)
#define IND     64
#define OUTD    64

// ---------------- scratch (static __device__ — no allocation allowed) -------
__device__ float g_Wc0[G4 * IND];              // W_ih0 @ W_in   (4096 x 64)
__device__ float g_bc0[G4];                    // W_ih0@b_in + b_ih0 + b_hh0
__device__ float g_pre0[(size_t)T_STEPS * G4]; // 64 MB
__device__ float g_pre1[(size_t)T_STEPS * G4]; // 64 MB
__device__ float g_H0[(size_t)T_STEPS * HH];   // 16 MB
__device__ float g_H1[(size_t)T_STEPS * HH];   // 16 MB
__device__ unsigned int g_ctr;

// ---------------- counter reset ---------------------------------------------
__global__ void k_reset() { g_ctr = 0u; }

// ---------------- Wc0 = W_ih0 @ W_in  (4096x1024 @ 1024x64 -> 4096x64) ------
__global__ __launch_bounds__(256) void k_wc0(const float* __restrict__ Wih0,
                                             const float* __restrict__ Win) {
    int tid = threadIdx.x;
    int tx = tid & 63;          // output col d
    int ty = tid >> 6;          // row within group of 4
    int r = blockIdx.x * 4 + ty;
    const float* wr = Wih0 + (size_t)r * HH;
    float acc = 0.f;
    for (int k = 0; k < HH; ++k)
        acc = fmaf(__ldg(&wr[k]), __ldg(&Win[k * IND + tx]), acc);
    g_Wc0[r * IND + tx] = acc;
}

// ---------------- bc0 = W_ih0 @ b_in + b_ih0 + b_hh0 ------------------------
__global__ __launch_bounds__(256) void k_bc0(const float* __restrict__ Wih0,
                                             const float* __restrict__ b_in,
                                             const float* __restrict__ b_ih0,
                                             const float* __restrict__ b_hh0) {
    int r = blockIdx.x * 256 + threadIdx.x;
    const float* wr = Wih0 + (size_t)r * HH;
    float acc = 0.f;
    for (int k = 0; k < HH; ++k)
        acc = fmaf(wr[k], __ldg(&b_in[k]), acc);
    g_bc0[r] = acc + b_ih0[r] + b_hh0[r];
}

// ---------------- pre0 = x @ Wc0^T + bc0   (M=4096, N=4096, K=64) -----------
__global__ __launch_bounds__(256) void k_pre0(const float* __restrict__ inp) {
    __shared__ float Xs[64][IND];
    __shared__ float Ws[64][IND];
    int tid = threadIdx.x;
    int t0 = blockIdx.y * 64;
    int r0 = blockIdx.x * 64;

    #pragma unroll
    for (int i = 0; i < 16; ++i) {
        int idx = tid + i * 256;
        int tr = idx >> 6, d = idx & 63;
        int t = t0 + tr;
        int s = t & 31, st = t >> 5;
        Xs[tr][d] = inp[((size_t)s * 128 + st) * 64 + d];
        Ws[tr][d] = g_Wc0[(r0 + tr) * IND + d];
    }
    __syncthreads();

    int tx = tid & 15, ty = tid >> 4;
    float acc[4][4] = {};
    for (int d = 0; d < 64; ++d) {
        float a[4], b[4];
        #pragma unroll
        for (int i = 0; i < 4; ++i) a[i] = Xs[ty * 4 + i][d];
        #pragma unroll
        for (int j = 0; j < 4; ++j) b[j] = Ws[tx * 4 + j][d];
        #pragma unroll
        for (int i = 0; i < 4; ++i)
            #pragma unroll
            for (int j = 0; j < 4; ++j)
                acc[i][j] = fmaf(a[i], b[j], acc[i][j]);
    }
    #pragma unroll
    for (int i = 0; i < 4; ++i) {
        int t = t0 + ty * 4 + i;
        #pragma unroll
        for (int j = 0; j < 4; ++j) {
            int r = r0 + tx * 4 + j;
            g_pre0[(size_t)t * G4 + r] = acc[i][j] + g_bc0[r];
        }
    }
}

// ---------------- fast activations ------------------------------------------
__device__ __forceinline__ float sigf(float x) {
    return __fdividef(1.f, 1.f + __expf(-x));
}
__device__ __forceinline__ float tanh_fast(float x) {
    float e = __expf(2.f * x);              // x>>0: e=inf -> 1-2/inf = 1  (ok)
    return 1.f - __fdividef(2.f, e + 1.f);  // x<<0: e=0   -> 1-2   = -1  (ok)
}

// ---------------- persistent LSTM chain -------------------------------------
// 128 CTAs x 1024 threads, grid-resident (1 CTA/SM).
// warp w owns gate row: unit ul=w>>2, gate g=w&3, global row = g*H + ubase+ul.
// lane l holds 16 packed weight pairs, pair j covers k = {64j+2l, 64j+2l+1}.
// Matvec = 16 fma.rn.f32x2, reduce = 1 shfl tree (no inter-warp reduce).
__global__ __launch_bounds__(1024, 1) void k_chain(const float* __restrict__ Whh,
                                                   const float* __restrict__ pre,
                                                   float* __restrict__ Hout) {
    int tid = threadIdx.x;
    int w = tid >> 5, l = tid & 31;
    int b = blockIdx.x;
    int ubase = b * UPC;
    int ul = w >> 2;          // local unit 0..7
    int g  = w & 3;           // gate 0..3 (i,f,g,o)
    int row = g * HH + ubase + ul;
    const float* wr = Whh + (size_t)row * HH;

    __shared__ float h_s[HH];
    __shared__ float gates[32];

    // resident packed weights: 16 x u64 (32 fp32)
    unsigned long long wp[16];
    #pragma unroll
    for (int j = 0; j < 16; ++j)
        wp[j] = *reinterpret_cast<const unsigned long long*>(wr + 64 * j + 2 * l);

    h_s[tid] = 0.f;
    float c = 0.f;                           // live only in warp0 lanes 0..7
    float preg = (l == 0) ? __ldg(&pre[row]) : 0.f;   // pre[t=0]
    __syncthreads();

    unsigned int* ctr = &g_ctr;

    for (int t = 0; t < T_STEPS; ++t) {
        // --- matvec: full gate row per warp, packed f32x2 -------------------
        unsigned long long a0 = 0ull, a1 = 0ull;
        #pragma unroll
        for (int j = 0; j < 16; j += 2) {
            unsigned long long h0 =
                *reinterpret_cast<const unsigned long long*>(&h_s[64 * j + 2 * l]);
            unsigned long long h1 =
                *reinterpret_cast<const unsigned long long*>(&h_s[64 * (j + 1) + 2 * l]);
            asm("fma.rn.f32x2 %0, %1, %2, %0;" : "+l"(a0) : "l"(wp[j]),     "l"(h0));
            asm("fma.rn.f32x2 %0, %1, %2, %0;" : "+l"(a1) : "l"(wp[j + 1]), "l"(h1));
        }
        unsigned long long at;
        asm("add.rn.f32x2 %0, %1, %2;" : "=l"(at) : "l"(a0), "l"(a1));
        float slo, shi;
        asm("mov.b64 {%0, %1}, %2;" : "=f"(slo), "=f"(shi) : "l"(at));
        float s = slo + shi;
        s += __shfl_xor_sync(0xffffffffu, s, 16);
        s += __shfl_xor_sync(0xffffffffu, s, 8);
        s += __shfl_xor_sync(0xffffffffu, s, 4);
        s += __shfl_xor_sync(0xffffffffu, s, 2);
        s += __shfl_xor_sync(0xffffffffu, s, 1);
        if (l == 0) {
            gates[w] = s + preg;
            // prefetch pre[t+1] — one full step of latency cover (DRAM-safe)
            if (t + 1 < T_STEPS)
                preg = __ldcg(&pre[(size_t)(t + 1) * G4 + row]);
        }
        __syncthreads();                                    // gates ready

        // --- cell: warp 0, lane u = unit ------------------------------------
        if (w == 0) {
            if (l < UPC) {
                float4 gv = *reinterpret_cast<const float4*>(&gates[4 * l]);
                float cn = sigf(gv.y) * c + sigf(gv.x) * tanh_fast(gv.z);
                c = cn;
                float h = sigf(gv.w) * tanh_fast(cn);
                Hout[(size_t)t * HH + ubase + l] = h;
            }
            __syncwarp();
            if (l == 0) {
                __threadfence();   // cumulative: carries lanes' h-stores (via syncwarp)
                asm volatile("red.relaxed.gpu.global.add.u32 [%0], 1;"
                             :: "l"(ctr) : "memory");
                unsigned int v, target = (unsigned int)(t + 1) * (unsigned int)NCTA;
                do {
                    asm volatile("ld.relaxed.gpu.global.u32 %0, [%1];"
                                 : "=r"(v) : "l"(ctr) : "memory");
                } while (v < target);
                __threadfence();   // acquire side
            }
        }
        __syncthreads();                                    // all CTAs arrived

        // --- broadcast: reload full h(t) from L2 ----------------------------
        h_s[tid] = __ldcg(&Hout[(size_t)t * HH + tid]);
        __syncthreads();                                    // h_s ready
    }
}

// ---------------- pre1 = H0 @ W_ih1^T + (b_ih1 + b_hh1) ---------------------
__global__ __launch_bounds__(256) void k_pre1(const float* __restrict__ A,
                                              const float* __restrict__ B,
                                              const float* __restrict__ b1a,
                                              const float* __restrict__ b1b) {
    __shared__ float As[2][8][132];
    __shared__ float Bs[2][8][132];
    int tid = threadIdx.x;
    int m0 = blockIdx.y * 128;
    int n0 = blockIdx.x * 128;
    int lm = tid >> 1;           // 0..127
    int kq = (tid & 1) * 4;      // 0 or 4
    int tx = tid & 15, ty = tid >> 4;

    const float* Ap = A + (size_t)(m0 + lm) * HH + kq;
    const float* Bp = B + (size_t)(n0 + lm) * HH + kq;

    float4 ra = *(const float4*)Ap;
    float4 rb = *(const float4*)Bp;
    As[0][kq + 0][lm] = ra.x; As[0][kq + 1][lm] = ra.y;
    As[0][kq + 2][lm] = ra.z; As[0][kq + 3][lm] = ra.w;
    Bs[0][kq + 0][lm] = rb.x; Bs[0][kq + 1][lm] = rb.y;
    Bs[0][kq + 2][lm] = rb.z; Bs[0][kq + 3][lm] = rb.w;
    __syncthreads();

    float acc[8][8] = {};
    const int nk = HH / 8;       // 128
    for (int kt = 0; kt < nk; ++kt) {
        int buf = kt & 1;
        if (kt + 1 < nk) {
            ra = *(const float4*)(Ap + (kt + 1) * 8);
            rb = *(const float4*)(Bp + (kt + 1) * 8);
        }
        #pragma unroll
        for (int kk = 0; kk < 8; ++kk) {
            float a[8], bb[8];
            *(float4*)&a[0]  = *(const float4*)&As[buf][kk][ty * 8];
            *(float4*)&a[4]  = *(const float4*)&As[buf][kk][ty * 8 + 4];
            *(float4*)&bb[0] = *(const float4*)&Bs[buf][kk][tx * 8];
            *(float4*)&bb[4] = *(const float4*)&Bs[buf][kk][tx * 8 + 4];
            #pragma unroll
            for (int i = 0; i < 8; ++i)
                #pragma unroll
                for (int j = 0; j < 8; ++j)
                    acc[i][j] = fmaf(a[i], bb[j], acc[i][j]);
        }
        __syncthreads();
        if (kt + 1 < nk) {
            int nb = buf ^ 1;
            As[nb][kq + 0][lm] = ra.x; As[nb][kq + 1][lm] = ra.y;
            As[nb][kq + 2][lm] = ra.z; As[nb][kq + 3][lm] = ra.w;
            Bs[nb][kq + 0][lm] = rb.x; Bs[nb][kq + 1][lm] = rb.y;
            Bs[nb][kq + 2][lm] = rb.z; Bs[nb][kq + 3][lm] = rb.w;
            __syncthreads();
        }
    }

    float bias[8];
    #pragma unroll
    for (int j = 0; j < 8; ++j) {
        int n = n0 + tx * 8 + j;
        bias[j] = __ldg(&b1a[n]) + __ldg(&b1b[n]);
    }
    #pragma unroll
    for (int i = 0; i < 8; ++i) {
        int m = m0 + ty * 8 + i;
        float4 o0, o1;
        o0.x = acc[i][0] + bias[0]; o0.y = acc[i][1] + bias[1];
        o0.z = acc[i][2] + bias[2]; o0.w = acc[i][3] + bias[3];
        o1.x = acc[i][4] + bias[4]; o1.y = acc[i][5] + bias[5];
        o1.z = acc[i][6] + bias[6]; o1.w = acc[i][7] + bias[7];
        *(float4*)&g_pre1[(size_t)m * G4 + n0 + tx * 8]     = o0;
        *(float4*)&g_pre1[(size_t)m * G4 + n0 + tx * 8 + 4] = o1;
    }
}

// ---------------- y = H1 @ W_out^T + b_out, reorder to (S, steps, O) --------
__global__ __launch_bounds__(256) void k_out(const float* __restrict__ Wout,
                                             const float* __restrict__ bout,
                                             float* __restrict__ out) {
    __shared__ float hs[HH];
    int t = blockIdx.x;
    int tid = threadIdx.x;
    #pragma unroll
    for (int i = 0; i < 4; ++i)
        hs[tid + i * 256] = g_H1[(size_t)t * HH + tid + i * 256];
    __syncthreads();

    int w = tid >> 5, l = tid & 31;
    int s = t & 31, st = t >> 5;
    float* orow = out + ((size_t)s * 128 + st) * 64;
    #pragma unroll
    for (int oi = 0; oi < 8; ++oi) {
        int o = w * 8 + oi;
        const float* wr = Wout + (size_t)o * HH;
        float acc = 0.f;
        #pragma unroll
        for (int j = 0; j < 32; ++j)
            acc = fmaf(__ldg(&wr[l + 32 * j]), hs[l + 32 * j], acc);
        acc += __shfl_xor_sync(0xffffffffu, acc, 16);
        acc += __shfl_xor_sync(0xffffffffu, acc, 8);
        acc += __shfl_xor_sync(0xffffffffu, acc, 4);
        acc += __shfl_xor_sync(0xffffffffu, acc, 2);
        acc += __shfl_xor_sync(0xffffffffu, acc, 1);
        if (l == 0) orow[o] = acc + __ldg(&bout[o]);
    }
}

// ---------------- launch ----------------------------------------------------
extern "C" void kernel_launch(void* const* d_in, const int* in_sizes, int n_in,
                              void* d_out, int out_size) {
    const float* inp   = (const float*)d_in[0];
    const float* W_in  = (const float*)d_in[1];
    const float* b_in  = (const float*)d_in[2];
    const float* W_ih0 = (const float*)d_in[3];
    const float* W_hh0 = (const float*)d_in[4];
    const float* b_ih0 = (const float*)d_in[5];
    const float* b_hh0 = (const float*)d_in[6];
    const float* W_ih1 = (const float*)d_in[7];
    const float* W_hh1 = (const float*)d_in[8];
    const float* b_ih1 = (const float*)d_in[9];
    const float* b_hh1 = (const float*)d_in[10];
    const float* W_out = (const float*)d_in[11];
    const float* b_out = (const float*)d_in[12];
    float* out = (float*)d_out;

    float *pre0, *pre1, *H0, *H1;
    cudaGetSymbolAddress((void**)&pre0, g_pre0);
    cudaGetSymbolAddress((void**)&pre1, g_pre1);
    cudaGetSymbolAddress((void**)&H0, g_H0);
    cudaGetSymbolAddress((void**)&H1, g_H1);

    // input-path GEMMs (K collapsed to 64 via Wc0 = W_ih0 @ W_in)
    k_wc0<<<G4 / 4, 256>>>(W_ih0, W_in);
    k_bc0<<<G4 / 256, 256>>>(W_ih0, b_in, b_ih0, b_hh0);
    k_pre0<<<dim3(64, 64), 256>>>(inp);

    // layer-0 sequential chain
    k_reset<<<1, 1>>>();
    k_chain<<<NCTA, 1024>>>(W_hh0, pre0, H0);

    // layer-1 input contributions (big fp32 GEMM)
    k_pre1<<<dim3(32, 32), 256>>>(H0, W_ih1, b_ih1, b_hh1);

    // layer-1 sequential chain
    k_reset<<<1, 1>>>();
    k_chain<<<NCTA, 1024>>>(W_hh1, pre1, H1);

    // output projection + (samples, steps, out) reorder
    k_out<<<T_STEPS, 256>>>(W_out, b_out, out);
}

// round 3
// speedup vs baseline: 1.2010x; 1.2010x over previous
#include <cuda_runtime.h>
#include <cstdint>
#include <cmath>

#define T_STEPS 4096
#define HH      1024
#define G4      4096          // 4*H gate rows
#define NCTA    128
#define UPC     8             // hidden units per CTA (1024/128)
#define IND     64
#define OUTD    64
#define PACCW   136           // padded pacc row stride (floats) — bank-conflict-free

// ---------------- scratch (static __device__ — no allocation allowed) -------
__device__ float g_Wc0[G4 * IND];              // W_ih0 @ W_in   (4096 x 64)
__device__ float g_bc0[G4];                    // W_ih0@b_in + b_ih0 + b_hh0
__device__ float g_pre0[(size_t)T_STEPS * G4]; // 64 MB
__device__ float g_pre1[(size_t)T_STEPS * G4]; // 64 MB
__device__ float g_H0[(size_t)T_STEPS * HH];   // 16 MB
__device__ float g_H1[(size_t)T_STEPS * HH];   // 16 MB
__device__ unsigned int g_ctr2[2];

// ---------------- counter reset (both chains' counters, launched FIRST) -----
__global__ void k_reset2() { g_ctr2[0] = 0u; g_ctr2[1] = 0u; }

// ---------------- Wc0 = W_ih0 @ W_in  (4096x1024 @ 1024x64 -> 4096x64) ------
__global__ __launch_bounds__(256) void k_wc0(const float* __restrict__ Wih0,
                                             const float* __restrict__ Win) {
    int tid = threadIdx.x;
    int tx = tid & 63;          // output col d
    int ty = tid >> 6;          // row within group of 4
    int r = blockIdx.x * 4 + ty;
    const float* wr = Wih0 + (size_t)r * HH;
    float acc = 0.f;
    for (int k = 0; k < HH; ++k)
        acc = fmaf(__ldg(&wr[k]), __ldg(&Win[k * IND + tx]), acc);
    g_Wc0[r * IND + tx] = acc;
}

// ---------------- bc0 = W_ih0 @ b_in + b_ih0 + b_hh0 ------------------------
__global__ __launch_bounds__(256) void k_bc0(const float* __restrict__ Wih0,
                                             const float* __restrict__ b_in,
                                             const float* __restrict__ b_ih0,
                                             const float* __restrict__ b_hh0) {
    int r = blockIdx.x * 256 + threadIdx.x;
    const float* wr = Wih0 + (size_t)r * HH;
    float acc = 0.f;
    for (int k = 0; k < HH; ++k)
        acc = fmaf(wr[k], __ldg(&b_in[k]), acc);
    g_bc0[r] = acc + b_ih0[r] + b_hh0[r];
}

// ---------------- pre0 = x @ Wc0^T + bc0   (M=4096, N=4096, K=64) -----------
// y0 = blockIdx.y offset (kernel split in two launches for ncu launch-index)
__global__ __launch_bounds__(256) void k_pre0(const float* __restrict__ inp, int y0) {
    __shared__ float Xs[64][IND];
    __shared__ float Ws[64][IND];
    int tid = threadIdx.x;
    int t0 = (blockIdx.y + y0) * 64;
    int r0 = blockIdx.x * 64;

    #pragma unroll
    for (int i = 0; i < 16; ++i) {
        int idx = tid + i * 256;
        int tr = idx >> 6, d = idx & 63;
        int t = t0 + tr;
        int s = t & 31, st = t >> 5;
        Xs[tr][d] = inp[((size_t)s * 128 + st) * 64 + d];
        Ws[tr][d] = g_Wc0[(r0 + tr) * IND + d];
    }
    __syncthreads();

    int tx = tid & 15, ty = tid >> 4;
    float acc[4][4] = {};
    for (int d = 0; d < 64; ++d) {
        float a[4], b[4];
        #pragma unroll
        for (int i = 0; i < 4; ++i) a[i] = Xs[ty * 4 + i][d];
        #pragma unroll
        for (int j = 0; j < 4; ++j) b[j] = Ws[tx * 4 + j][d];
        #pragma unroll
        for (int i = 0; i < 4; ++i)
            #pragma unroll
            for (int j = 0; j < 4; ++j)
                acc[i][j] = fmaf(a[i], b[j], acc[i][j]);
    }
    #pragma unroll
    for (int i = 0; i < 4; ++i) {
        int t = t0 + ty * 4 + i;
        #pragma unroll
        for (int j = 0; j < 4; ++j) {
            int r = r0 + tx * 4 + j;
            g_pre0[(size_t)t * G4 + r] = acc[i][j] + g_bc0[r];
        }
    }
}

// ---------------- fast activations ------------------------------------------
__device__ __forceinline__ float sigf(float x) {
    return __fdividef(1.f, 1.f + __expf(-x));
}
__device__ __forceinline__ float tanh_fast(float x) {
    float e = __expf(2.f * x);
    return 1.f - __fdividef(2.f, e + 1.f);
}

// ---------------- persistent LSTM chain -------------------------------------
// 128 CTAs x 1024 threads, grid-resident (1 CTA/SM).
// Matvec (R1 layout): warp w: unit ul=w>>2, k-quarter q=w&3; lane l covers
// k = [q*256 + l*8, +8) for all 4 gates of unit ul. Weights: 16 packed u64.
// Reduce+cell fused: warp u<8 owns unit u; lane = (gate g=l>>3, seg j=l&7);
// pacc padded to 136 floats/row -> conflict-free strided reads.
__global__ __launch_bounds__(1024, 1) void k_chain(const float* __restrict__ Whh,
                                                   const float* __restrict__ pre,
                                                   float* __restrict__ Hout,
                                                   int ctr_idx) {
    int tid = threadIdx.x;
    int w = tid >> 5, l = tid & 31;
    int b = blockIdx.x;
    int ubase = b * UPC;
    int ul = w >> 2;          // matvec: local unit 0..7
    int q  = w & 3;           // matvec: k-quarter 0..3
    int unit = ubase + ul;
    int koff = q * 256 + l * 8;

    __shared__ float h_s[HH];
    __shared__ float pacc[32 * PACCW];

    // resident packed weights: gate g, pair j covers k = koff + 2j{,+1}
    unsigned long long wp[4][4];
    #pragma unroll
    for (int g = 0; g < 4; ++g) {
        const float* wr = Whh + (size_t)(g * HH + unit) * HH + koff;
        ulonglong2 v0 = *reinterpret_cast<const ulonglong2*>(wr);
        ulonglong2 v1 = *reinterpret_cast<const ulonglong2*>(wr + 4);
        wp[g][0] = v0.x; wp[g][1] = v0.y; wp[g][2] = v1.x; wp[g][3] = v1.y;
    }

    // reduce/cell role constants (warps 0..7)
    int rg = l >> 3;                 // gate 0..3
    int rj = l & 7;                  // segment 0..7
    int grow = rg * HH + ubase + w;  // global gate row for this reduce warp
    float preg = 0.f;
    if (w < UPC && rj == 0) preg = __ldg(&pre[grow]);   // pre[t=0]
    float c = 0.f;                   // cell state: warp u lane 0

    h_s[tid] = 0.f;
    __syncthreads();

    unsigned int* ctr = &g_ctr2[ctr_idx];

    for (int t = 0; t < T_STEPS; ++t) {
        // --- matvec: packed f32x2, 16 FFMA2 ---------------------------------
        ulonglong2 hv0 = *reinterpret_cast<const ulonglong2*>(&h_s[koff]);
        ulonglong2 hv1 = *reinterpret_cast<const ulonglong2*>(&h_s[koff + 4]);
        unsigned long long hu0 = hv0.x, hu1 = hv0.y, hu2 = hv1.x, hu3 = hv1.y;
        unsigned long long acc[4] = {0ull, 0ull, 0ull, 0ull};
        #pragma unroll
        for (int g = 0; g < 4; ++g) {
            asm("fma.rn.f32x2 %0, %1, %2, %0;" : "+l"(acc[g]) : "l"(wp[g][0]), "l"(hu0));
            asm("fma.rn.f32x2 %0, %1, %2, %0;" : "+l"(acc[g]) : "l"(wp[g][1]), "l"(hu1));
            asm("fma.rn.f32x2 %0, %1, %2, %0;" : "+l"(acc[g]) : "l"(wp[g][2]), "l"(hu2));
            asm("fma.rn.f32x2 %0, %1, %2, %0;" : "+l"(acc[g]) : "l"(wp[g][3]), "l"(hu3));
        }
        #pragma unroll
        for (int g = 0; g < 4; ++g) {
            float lo, hi;
            asm("mov.b64 {%0, %1}, %2;" : "=f"(lo), "=f"(hi) : "l"(acc[g]));
            pacc[(ul * 4 + g) * PACCW + q * 32 + l] = lo + hi;
        }
        __syncthreads();                                 // BAR1: pacc ready

        // --- fused reduce + cell: warp u (<8) owns unit u -------------------
        if (w < UPC) {
            int prow = (w * 4 + rg) * PACCW;
            float s = 0.f;
            #pragma unroll
            for (int i = 0; i < 16; ++i)
                s += pacc[prow + 8 * i + rj];
            s += __shfl_xor_sync(0xffffffffu, s, 4);
            s += __shfl_xor_sync(0xffffffffu, s, 2);
            s += __shfl_xor_sync(0xffffffffu, s, 1);
            if (rj == 0) {
                s += preg;
                if (t + 1 < T_STEPS)                      // prefetch pre[t+1]
                    preg = __ldcg(&pre[(size_t)(t + 1) * G4 + grow]);
            }
            float gi = __shfl_sync(0xffffffffu, s, 0);
            float gf = __shfl_sync(0xffffffffu, s, 8);
            float gg = __shfl_sync(0xffffffffu, s, 16);
            float go = __shfl_sync(0xffffffffu, s, 24);
            if (l == 0) {
                float cn = sigf(gf) * c + sigf(gi) * tanh_fast(gg);
                c = cn;
                float h = sigf(go) * tanh_fast(cn);
                __stcg(&Hout[(size_t)t * HH + ubase + w], h);
            }
        }
        __syncthreads();                                 // BAR2: all h stored

        // --- chip-wide sync: release-arrive + acquire-poll (tid 0 only) -----
        if (tid == 0) {
            asm volatile("red.release.gpu.global.add.u32 [%0], 1;"
                         :: "l"(ctr) : "memory");
            unsigned int v, target = (unsigned int)(t + 1) * (unsigned int)NCTA;
            do {
                asm volatile("ld.acquire.gpu.global.u32 %0, [%1];"
                             : "=r"(v) : "l"(ctr) : "memory");
            } while (v < target);
        }
        __syncthreads();                                 // BAR3: sync done

        // --- broadcast: reload full h(t) from L2 ----------------------------
        h_s[tid] = __ldcg(&Hout[(size_t)t * HH + tid]);
        __syncthreads();                                 // BAR4: h_s ready
    }
}

// ---------------- pre1 = H0 @ W_ih1^T + (b_ih1 + b_hh1) ---------------------
// M=N=4096, K=1024, fp32, 128x128 tile, 8x8 micro, f32x2 packed FMA.
__global__ __launch_bounds__(256) void k_pre1(const float* __restrict__ A,
                                              const float* __restrict__ B,
                                              const float* __restrict__ b1a,
                                              const float* __restrict__ b1b) {
    __shared__ float As[2][8][132];
    __shared__ float Bs[2][8][132];
    int tid = threadIdx.x;
    int m0 = blockIdx.y * 128;
    int n0 = blockIdx.x * 128;
    int lm = tid >> 1;           // 0..127
    int kq = (tid & 1) * 4;      // 0 or 4
    int tx = tid & 15, ty = tid >> 4;

    const float* Ap = A + (size_t)(m0 + lm) * HH + kq;
    const float* Bp = B + (size_t)(n0 + lm) * HH + kq;

    float4 ra = *(const float4*)Ap;
    float4 rb = *(const float4*)Bp;
    As[0][kq + 0][lm] = ra.x; As[0][kq + 1][lm] = ra.y;
    As[0][kq + 2][lm] = ra.z; As[0][kq + 3][lm] = ra.w;
    Bs[0][kq + 0][lm] = rb.x; Bs[0][kq + 1][lm] = rb.y;
    Bs[0][kq + 2][lm] = rb.z; Bs[0][kq + 3][lm] = rb.w;
    __syncthreads();

    unsigned long long accp[8][4];
    #pragma unroll
    for (int i = 0; i < 8; ++i)
        #pragma unroll
        for (int j = 0; j < 4; ++j) accp[i][j] = 0ull;

    const int nk = HH / 8;       // 128
    for (int kt = 0; kt < nk; ++kt) {
        int buf = kt & 1;
        if (kt + 1 < nk) {
            ra = *(const float4*)(Ap + (kt + 1) * 8);
            rb = *(const float4*)(Bp + (kt + 1) * 8);
        }
        #pragma unroll
        for (int kk = 0; kk < 8; ++kk) {
            float a[8];
            *(float4*)&a[0] = *(const float4*)&As[buf][kk][ty * 8];
            *(float4*)&a[4] = *(const float4*)&As[buf][kk][ty * 8 + 4];
            unsigned long long bbv[4];
            {
                ulonglong2 b0 = *(const ulonglong2*)&Bs[buf][kk][tx * 8];
                ulonglong2 b1 = *(const ulonglong2*)&Bs[buf][kk][tx * 8 + 4];
                bbv[0] = b0.x; bbv[1] = b0.y; bbv[2] = b1.x; bbv[3] = b1.y;
            }
            #pragma unroll
            for (int i = 0; i < 8; ++i) {
                unsigned long long aa;
                asm("mov.b64 %0, {%1, %1};" : "=l"(aa) : "f"(a[i]));
                #pragma unroll
                for (int j = 0; j < 4; ++j)
                    asm("fma.rn.f32x2 %0, %1, %2, %0;"
                        : "+l"(accp[i][j]) : "l"(aa), "l"(bbv[j]));
            }
        }
        __syncthreads();
        if (kt + 1 < nk) {
            int nb = buf ^ 1;
            As[nb][kq + 0][lm] = ra.x; As[nb][kq + 1][lm] = ra.y;
            As[nb][kq + 2][lm] = ra.z; As[nb][kq + 3][lm] = ra.w;
            Bs[nb][kq + 0][lm] = rb.x; Bs[nb][kq + 1][lm] = rb.y;
            Bs[nb][kq + 2][lm] = rb.z; Bs[nb][kq + 3][lm] = rb.w;
            __syncthreads();
        }
    }

    float bias[8];
    #pragma unroll
    for (int j = 0; j < 8; ++j) {
        int n = n0 + tx * 8 + j;
        bias[j] = __ldg(&b1a[n]) + __ldg(&b1b[n]);
    }
    #pragma unroll
    for (int i = 0; i < 8; ++i) {
        int m = m0 + ty * 8 + i;
        float o[8];
        #pragma unroll
        for (int j = 0; j < 4; ++j) {
            float lo, hi;
            asm("mov.b64 {%0, %1}, %2;" : "=f"(lo), "=f"(hi) : "l"(accp[i][j]));
            o[2 * j] = lo + bias[2 * j];
            o[2 * j + 1] = hi + bias[2 * j + 1];
        }
        *(float4*)&g_pre1[(size_t)m * G4 + n0 + tx * 8]     = *(float4*)&o[0];
        *(float4*)&g_pre1[(size_t)m * G4 + n0 + tx * 8 + 4] = *(float4*)&o[4];
    }
}

// ---------------- y = H1 @ W_out^T + b_out, reorder to (S, steps, O) --------
__global__ __launch_bounds__(256) void k_out(const float* __restrict__ Wout,
                                             const float* __restrict__ bout,
                                             float* __restrict__ out) {
    __shared__ float hs[HH];
    int t = blockIdx.x;
    int tid = threadIdx.x;
    #pragma unroll
    for (int i = 0; i < 4; ++i)
        hs[tid + i * 256] = g_H1[(size_t)t * HH + tid + i * 256];
    __syncthreads();

    int w = tid >> 5, l = tid & 31;
    int s = t & 31, st = t >> 5;
    float* orow = out + ((size_t)s * 128 + st) * 64;
    #pragma unroll
    for (int oi = 0; oi < 8; ++oi) {
        int o = w * 8 + oi;
        const float* wr = Wout + (size_t)o * HH;
        float acc = 0.f;
        #pragma unroll
        for (int j = 0; j < 32; ++j)
            acc = fmaf(__ldg(&wr[l + 32 * j]), hs[l + 32 * j], acc);
        acc += __shfl_xor_sync(0xffffffffu, acc, 16);
        acc += __shfl_xor_sync(0xffffffffu, acc, 8);
        acc += __shfl_xor_sync(0xffffffffu, acc, 4);
        acc += __shfl_xor_sync(0xffffffffu, acc, 2);
        acc += __shfl_xor_sync(0xffffffffu, acc, 1);
        if (l == 0) orow[o] = acc + __ldg(&bout[o]);
    }
}

// ---------------- launch ----------------------------------------------------
// Launch order chosen so ncu (-s 5) captures k_chain (launch index 5).
extern "C" void kernel_launch(void* const* d_in, const int* in_sizes, int n_in,
                              void* d_out, int out_size) {
    const float* inp   = (const float*)d_in[0];
    const float* W_in  = (const float*)d_in[1];
    const float* b_in  = (const float*)d_in[2];
    const float* W_ih0 = (const float*)d_in[3];
    const float* W_hh0 = (const float*)d_in[4];
    const float* b_ih0 = (const float*)d_in[5];
    const float* b_hh0 = (const float*)d_in[6];
    const float* W_ih1 = (const float*)d_in[7];
    const float* W_hh1 = (const float*)d_in[8];
    const float* b_ih1 = (const float*)d_in[9];
    const float* b_hh1 = (const float*)d_in[10];
    const float* W_out = (const float*)d_in[11];
    const float* b_out = (const float*)d_in[12];
    float* out = (float*)d_out;

    float *pre0, *pre1, *H0, *H1;
    cudaGetSymbolAddress((void**)&pre0, g_pre0);
    cudaGetSymbolAddress((void**)&pre1, g_pre1);
    cudaGetSymbolAddress((void**)&H0, g_H0);
    cudaGetSymbolAddress((void**)&H1, g_H1);

    k_reset2<<<1, 1>>>();                                   // 0
    k_wc0<<<G4 / 4, 256>>>(W_ih0, W_in);                    // 1
    k_bc0<<<G4 / 256, 256>>>(W_ih0, b_in, b_ih0, b_hh0);    // 2
    k_pre0<<<dim3(64, 32), 256>>>(inp, 0);                  // 3
    k_pre0<<<dim3(64, 32), 256>>>(inp, 32);                 // 4

    k_chain<<<NCTA, 1024>>>(W_hh0, pre0, H0, 0);            // 5  <- ncu capture

    k_pre1<<<dim3(32, 32), 256>>>(H0, W_ih1, b_ih1, b_hh1); // 6
    k_chain<<<NCTA, 1024>>>(W_hh1, pre1, H1, 1);            // 7
    k_out<<<T_STEPS, 256>>>(W_out, b_out, out);             // 8
}